// round 8
// baseline (speedup 1.0000x reference)
#include <cuda_runtime.h>
#include <cuda_bf16.h>
#include <cstdint>

#define MAX_NU 160000
#define MAX_NM 60000
#define MAX_E  5000000
#define DIM 64
#define COEF (13.0f / 12.0f)   // 1/2 + 1/3 + 1/4 : all layers aggregate layer-0 feats

#define SCAN_TILE 2048          // elements per scan block (256 threads x 8)

// ---- scratch (static device globals; zero-initialized at module load) ------
__device__ int   g_deg_u[MAX_NU];      // must be 0 at entry; re-zeroed at end of run
__device__ int   g_deg_m[MAX_NM];
__device__ float g_inv_u[MAX_NU];
__device__ float g_inv_m[MAX_NM];
__device__ int   g_off_u[MAX_NU + 1];  // exclusive offsets; consumed as cursors by fill
__device__ int   g_off_m[MAX_NM + 1];
__device__ int   g_nbr_u[MAX_E];       // per user: movie neighbors
__device__ int   g_nbr_m[MAX_E];       // per movie: user neighbors
__device__ int   g_bsum_u[256];
__device__ int   g_bsum_m[128];
// bf16 staged source rows, PRE-SCALED by inv_src. Row = 64 bf16 = 16 uint2.
__device__ uint2 g_xm_bf[MAX_NM * 16];   // 7.68 MB
__device__ uint2 g_xu_bf[MAX_NU * 16];   // 20.5 MB

// ---------------------------------------------------------------------------
// 1. count degrees: RED (no return), 2 edges per iteration
__global__ void k_count_deg(const int2* __restrict__ ef2, const int2* __restrict__ et2,
                            const int* __restrict__ ef, const int* __restrict__ et,
                            int E) {
    int E2 = E >> 1;
    int i = blockIdx.x * blockDim.x + threadIdx.x;
    int stride = gridDim.x * blockDim.x;
    for (; i < E2; i += stride) {
        int2 f = __ldg(&ef2[i]);
        int2 t = __ldg(&et2[i]);
        atomicAdd(&g_deg_m[f.x], 1);
        atomicAdd(&g_deg_m[f.y], 1);
        atomicAdd(&g_deg_u[t.x], 1);
        atomicAdd(&g_deg_u[t.y], 1);
    }
    if (i == E2 && (E & 1)) {
        atomicAdd(&g_deg_m[ef[E - 1]], 1);
        atomicAdd(&g_deg_u[et[E - 1]], 1);
    }
}

// ---- parallel exclusive scan, 3 phases -------------------------------------
__global__ void k_scan_part(int nu, int nm, int Bu) {
    __shared__ int sh[256];
    int b = blockIdx.x;
    const int* deg; int* off; int* bsum; int n; int lb;
    if (b < Bu) { deg = g_deg_u; off = g_off_u; bsum = g_bsum_u; n = nu; lb = b; }
    else        { deg = g_deg_m; off = g_off_m; bsum = g_bsum_m; n = nm; lb = b - Bu; }

    int t = threadIdx.x;
    int idx = lb * SCAN_TILE + t * 8;
    int v[8], s = 0;
    #pragma unroll
    for (int j = 0; j < 8; j++) {
        v[j] = (idx + j < n) ? deg[idx + j] : 0;
        s += v[j];
    }
    sh[t] = s;
    __syncthreads();
    #pragma unroll
    for (int o = 1; o < 256; o <<= 1) {
        int tmp = (t >= o) ? sh[t - o] : 0;
        __syncthreads();
        sh[t] += tmp;
        __syncthreads();
    }
    int ex = sh[t] - s;
    #pragma unroll
    for (int j = 0; j < 8; j++) {
        if (idx + j < n) off[idx + j] = ex;
        ex += v[j];
    }
    if (t == 255) bsum[lb] = sh[255];
}

__global__ void k_scan_bsum(int Bu, int Bm, int nu, int nm) {
    if (threadIdx.x == 0) {
        int acc = 0;
        for (int i = 0; i < Bu; i++) { int v = g_bsum_u[i]; g_bsum_u[i] = acc; acc += v; }
        g_off_u[nu] = acc;
    }
    if (threadIdx.x == 1) {
        int acc = 0;
        for (int i = 0; i < Bm; i++) { int v = g_bsum_m[i]; g_bsum_m[i] = acc; acc += v; }
        g_off_m[nm] = acc;
    }
}

// Phase C: add tile prefix to off, compute inv = rsqrt(deg)
__global__ void k_scan_add(int nu, int nm, int Bu) {
    int b = blockIdx.x;
    const int* deg; int* off; float* inv; const int* bsum; int n; int lb;
    if (b < Bu) { deg = g_deg_u; off = g_off_u; inv = g_inv_u; bsum = g_bsum_u; n = nu; lb = b; }
    else        { deg = g_deg_m; off = g_off_m; inv = g_inv_m; bsum = g_bsum_m; n = nm; lb = b - Bu; }

    int add = bsum[lb];
    int idx = lb * SCAN_TILE + threadIdx.x * 8;
    #pragma unroll
    for (int j = 0; j < 8; j++) {
        int i = idx + j;
        if (i < n) {
            off[i] += add;
            int d = deg[i];
            inv[i] = (d > 0) ? rsqrtf((float)d) : 0.0f;
        }
    }
}

// ---- fused convert + fill --------------------------------------------------
// Blocks [0, fillB): CSR fill (atomics on off itself; post-fill off[i] = orig off[i+1]).
// Blocks [fillB, fillB+convB): stage pre-scaled bf16 rows.
__global__ void k_convfill(const int2* __restrict__ ef2, const int2* __restrict__ et2,
                           const int* __restrict__ ef, const int* __restrict__ et, int E,
                           const float4* __restrict__ xu, const float4* __restrict__ xm,
                           int nu, int nm, int fillB) {
    if (blockIdx.x < fillB) {
        // ---- fill path ----
        int E2 = E >> 1;
        int i = blockIdx.x * blockDim.x + threadIdx.x;
        int stride = fillB * blockDim.x;
        for (; i < E2; i += stride) {
            int2 f = __ldg(&ef2[i]);
            int2 t = __ldg(&et2[i]);
            int pu0 = atomicAdd(&g_off_u[t.x], 1);
            int pu1 = atomicAdd(&g_off_u[t.y], 1);
            int pm0 = atomicAdd(&g_off_m[f.x], 1);
            int pm1 = atomicAdd(&g_off_m[f.y], 1);
            g_nbr_u[pu0] = f.x;
            g_nbr_u[pu1] = f.y;
            g_nbr_m[pm0] = t.x;
            g_nbr_m[pm1] = t.y;
        }
        if (i == E2 && (E & 1)) {
            int f = ef[E - 1], t = et[E - 1];
            int pu = atomicAdd(&g_off_u[t], 1);
            g_nbr_u[pu] = f;
            int pm = atomicAdd(&g_off_m[f], 1);
            g_nbr_m[pm] = t;
        }
    } else {
        // ---- convert path ----
        int i = (blockIdx.x - fillB) * blockDim.x + threadIdx.x;
        int total_u = nu * 16;
        int total   = total_u + nm * 16;
        if (i >= total) return;
        const float4* src; const float* inv; uint2* dst; int node, chunk;
        if (i < total_u) { src = xu; inv = g_inv_u; dst = g_xu_bf; node = i >> 4; chunk = i & 15; }
        else { int j = i - total_u; src = xm; inv = g_inv_m; dst = g_xm_bf; node = j >> 4; chunk = j & 15; }

        float sc = inv[node];
        float4 v = src[node * 16 + chunk];
        __nv_bfloat162 b0 = __floats2bfloat162_rn(sc * v.x, sc * v.y);
        __nv_bfloat162 b1 = __floats2bfloat162_rn(sc * v.z, sc * v.w);
        uint2 p;
        p.x = *(unsigned int*)&b0;
        p.y = *(unsigned int*)&b1;
        dst[node * 16 + chunk] = p;
    }
}

// ---- merged gather: one warp per node, half-warps over neighbors -----------
// 3-wide unroll per half (6 rows in flight per warp), bit-shift bf16->f32.
// Bounds: start = node ? off[node-1] : 0, end = off[node]  (post-fill offsets)
__device__ __forceinline__ void acc_word(float4& acc, uint2 p) {
    acc.x += __uint_as_float(p.x << 16);
    acc.y += __uint_as_float(p.x & 0xFFFF0000u);
    acc.z += __uint_as_float(p.y << 16);
    acc.w += __uint_as_float(p.y & 0xFFFF0000u);
}

__global__ void __launch_bounds__(256)
k_gather_all(const float4* __restrict__ xu, const float4* __restrict__ xm,
             float4* __restrict__ ru, float4* __restrict__ rm,
             int nu, int nm)
{
    int gtid = blockIdx.x * blockDim.x + threadIdx.x;
    int w = gtid >> 5;
    if (w >= nu + nm) return;
    int lane = threadIdx.x & 31;
    int half = lane >> 4;
    int l    = lane & 15;

    const int* nbr; const int* roff; const uint2* src;
    const float4* xself; const float* inv_self; float4* out; int node;
    if (w < nu) {
        node = w; nbr = g_nbr_u; roff = g_off_u; src = g_xm_bf;
        xself = xu; inv_self = g_inv_u; out = ru;
    } else {
        node = w - nu; nbr = g_nbr_m; roff = g_off_m; src = g_xu_bf;
        xself = xm; inv_self = g_inv_m; out = rm;
    }

    int s = (node == 0) ? 0 : __ldg(&roff[node - 1]);
    int e = __ldg(&roff[node]);

    float4 acc0 = make_float4(0.f, 0.f, 0.f, 0.f);
    float4 acc1 = make_float4(0.f, 0.f, 0.f, 0.f);
    float4 acc2 = make_float4(0.f, 0.f, 0.f, 0.f);

    int i = s + half;
    // 3 neighbors in flight per half-warp (6 per warp)
    for (; i + 4 < e; i += 6) {
        int f0 = __ldg(&nbr[i]);
        int f1 = __ldg(&nbr[i + 2]);
        int f2 = __ldg(&nbr[i + 4]);
        uint2 p0 = __ldg(&src[f0 * 16 + l]);
        uint2 p1 = __ldg(&src[f1 * 16 + l]);
        uint2 p2 = __ldg(&src[f2 * 16 + l]);
        acc_word(acc0, p0);
        acc_word(acc1, p1);
        acc_word(acc2, p2);
    }
    for (; i < e; i += 2) {
        int f = __ldg(&nbr[i]);
        uint2 p = __ldg(&src[f * 16 + l]);
        acc_word(acc0, p);
    }
    acc0.x += acc1.x + acc2.x;
    acc0.y += acc1.y + acc2.y;
    acc0.z += acc1.z + acc2.z;
    acc0.w += acc1.w + acc2.w;

    __syncwarp();
    acc0.x += __shfl_xor_sync(0xFFFFFFFFu, acc0.x, 16);
    acc0.y += __shfl_xor_sync(0xFFFFFFFFu, acc0.y, 16);
    acc0.z += __shfl_xor_sync(0xFFFFFFFFu, acc0.z, 16);
    acc0.w += __shfl_xor_sync(0xFFFFFFFFu, acc0.w, 16);

    if (half == 0) {
        float4 xs = xself[node * 16 + l];
        float c = COEF * inv_self[node];
        float4 r;
        r.x = fmaf(c, acc0.x, xs.x);
        r.y = fmaf(c, acc0.y, xs.y);
        r.z = fmaf(c, acc0.z, xs.z);
        r.w = fmaf(c, acc0.w, xs.w);
        out[node * 16 + l] = r;
    }
}

// ---- scores ----------------------------------------------------------------
__global__ void k_scores(const int* __restrict__ lm, const int* __restrict__ lu,
                         const float2* __restrict__ ru, const float2* __restrict__ rm,
                         float* __restrict__ out, int L) {
    int gtid = blockIdx.x * blockDim.x + threadIdx.x;
    int l    = gtid >> 5;
    int lane = threadIdx.x & 31;
    if (l >= L) return;

    int m = lm[l];
    int u = lu[l];
    float2 a = __ldg(&ru[u * 32 + lane]);
    float2 b = __ldg(&rm[m * 32 + lane]);
    float s = a.x * b.x + a.y * b.y;

    #pragma unroll
    for (int off = 16; off > 0; off >>= 1)
        s += __shfl_down_sync(0xFFFFFFFFu, s, off);

    if (lane == 0) out[l] = s;
}

// ---- trailing zero: restore deg arrays for the next run --------------------
__global__ void k_zero_deg(int nu, int nm) {
    int i = blockIdx.x * blockDim.x + threadIdx.x;
    if (i < nu) g_deg_u[i] = 0;
    if (i < nm) g_deg_m[i] = 0;
}

// ---------------------------------------------------------------------------
extern "C" void kernel_launch(void* const* d_in, const int* in_sizes, int n_in,
                              void* d_out, int out_size) {
    const float* emb_user  = (const float*)d_in[0];   // [NU, 64]
    const float* emb_movie = (const float*)d_in[1];   // [NM, 64]
    const int* edge_from   = (const int*)d_in[4];     // [E] movie idx
    const int* edge_to     = (const int*)d_in[5];     // [E] user idx
    const int* label_movie = (const int*)d_in[6];     // [L]
    const int* label_user  = (const int*)d_in[7];     // [L]

    int NU = in_sizes[0] / DIM;
    int NM = in_sizes[1] / DIM;
    int E  = in_sizes[4];
    int L  = in_sizes[6];

    float* out    = (float*)d_out;
    float* scores = out;                    // [L]
    float* res_u  = out + L;                // [NU*64]
    float* res_m  = out + L + NU * DIM;     // [NM*64]

    int Bu = (NU + SCAN_TILE - 1) / SCAN_TILE;
    int Bm = (NM + SCAN_TILE - 1) / SCAN_TILE;
    int nmax = (NU > NM) ? NU : NM;

    // deg arrays are zero at entry (module-load init for run 1; trailing
    // k_zero_deg restores them at the end of every run).

    // 1
    k_count_deg<<<2048, 256>>>((const int2*)edge_from, (const int2*)edge_to,
                               edge_from, edge_to, E);
    // 2,3,4
    k_scan_part<<<Bu + Bm, 256>>>(NU, NM, Bu);
    k_scan_bsum<<<1, 32>>>(Bu, Bm, NU, NM);
    k_scan_add<<<Bu + Bm, 256>>>(NU, NM, Bu);

    // 5: fused convert + fill (fill blocks first — longer pole starts first)
    {
        int fillB = 2048;
        int convB = ((NU + NM) * 16 + 255) / 256;
        k_convfill<<<fillB + convB, 256>>>((const int2*)edge_from, (const int2*)edge_to,
                                           edge_from, edge_to, E,
                                           (const float4*)emb_user, (const float4*)emb_movie,
                                           NU, NM, fillB);
    }

    // 6: merged gather (ncu capture slot)
    {
        long long threads = (long long)(NU + NM) * 32;
        int blocks = (int)((threads + 255) / 256);
        k_gather_all<<<blocks, 256>>>((const float4*)emb_user, (const float4*)emb_movie,
                                      (float4*)res_u, (float4*)res_m, NU, NM);
    }

    // 7
    {
        long long threads = (long long)L * 32;
        int blocks = (int)((threads + 255) / 256);
        k_scores<<<blocks, 256>>>(label_movie, label_user,
                                  (const float2*)res_u, (const float2*)res_m,
                                  scores, L);
    }

    // 8: restore deg arrays for next run
    k_zero_deg<<<(nmax + 255) / 256, 256>>>(NU, NM);
}